// round 13
// baseline (speedup 1.0000x reference)
#include <cuda_runtime.h>
#include <cuda_fp16.h>
#include <cstdint>
#include <math.h>

// Problem constants
#define B_  2
#define T_  2048
#define D_  4096
#define H_  32
#define KVH_ 8
#define HD_ 128
#define BT_ (B_ * T_)            // 4096
#define NQKV (D_ + 2 * KVH_ * HD_)   // 6144

// Scratch (allocation-free: __device__ globals) — fp16 pipeline
__device__ __half g_qh[(size_t)BT_ * H_ * HD_];     // [B,T,H,HD]
__device__ __half g_kh[(size_t)BT_ * KVH_ * HD_];   // [B,T,KVH,HD]
__device__ __half g_vh[(size_t)BT_ * KVH_ * HD_];
__device__ __half g_ctxh[(size_t)BT_ * H_ * HD_];   // [B,T,H*HD]
__device__ __half g_xh[(size_t)BT_ * D_];
__device__ __half g_wf[(size_t)NQKV * D_];          // fused [wq;wk;wv]
__device__ __half g_woh[(size_t)D_ * D_];

// ---------------------------------------------------------------------------
// helpers
// ---------------------------------------------------------------------------
__device__ __forceinline__ float ex2f(float x) {
    float y;
    asm("ex2.approx.ftz.f32 %0, %1;" : "=f"(y) : "f"(x));
    return y;
}
__device__ __forceinline__ void mma_f16(float* d, const uint32_t* a,
                                        const uint32_t* b, const float* c) {
    asm volatile(
        "mma.sync.aligned.m16n8k16.row.col.f32.f16.f16.f32 "
        "{%0,%1,%2,%3}, {%4,%5,%6,%7}, {%8,%9}, {%10,%11,%12,%13};"
        : "=f"(d[0]), "=f"(d[1]), "=f"(d[2]), "=f"(d[3])
        : "r"(a[0]), "r"(a[1]), "r"(a[2]), "r"(a[3]),
          "r"(b[0]), "r"(b[1]),
          "f"(c[0]), "f"(c[1]), "f"(c[2]), "f"(c[3]));
}
__device__ __forceinline__ void ldsm_x4(uint32_t& r0, uint32_t& r1,
                                        uint32_t& r2, uint32_t& r3, uint32_t addr) {
    asm volatile("ldmatrix.sync.aligned.m8n8.x4.shared.b16 {%0,%1,%2,%3}, [%4];"
                 : "=r"(r0), "=r"(r1), "=r"(r2), "=r"(r3) : "r"(addr));
}
__device__ __forceinline__ void ldsm_x4_t(uint32_t& r0, uint32_t& r1,
                                          uint32_t& r2, uint32_t& r3, uint32_t addr) {
    asm volatile("ldmatrix.sync.aligned.m8n8.x4.trans.shared.b16 {%0,%1,%2,%3}, [%4];"
                 : "=r"(r0), "=r"(r1), "=r"(r2), "=r"(r3) : "r"(addr));
}
__device__ __forceinline__ void cp16s(uint32_t saddr, const void* gmem_src) {
    asm volatile("cp.async.cg.shared.global [%0], [%1], 16;" :: "r"(saddr), "l"(gmem_src));
}
#define CP_COMMIT() asm volatile("cp.async.commit_group;" ::: "memory")
template <int N>
__device__ __forceinline__ void cp_wait() {
    asm volatile("cp.async.wait_group %0;" :: "n"(N) : "memory");
}
__device__ __forceinline__ uint32_t smem_u32(const void* p) {
    return (uint32_t)__cvta_generic_to_shared(p);
}
__device__ __forceinline__ uint32_t pack_h2(float a, float b) {
    __half2 h = __floats2half2_rn(a, b);
    return *(uint32_t*)&h;
}

// ---------------------------------------------------------------------------
// fp32 -> fp16 conversion pass
// ---------------------------------------------------------------------------
__global__ void f2h_kernel(const float4* __restrict__ src,
                           uint2* __restrict__ dst, int n4)
{
    int i = blockIdx.x * blockDim.x + threadIdx.x;
    if (i >= n4) return;
    float4 v = src[i];
    uint2 o;
    o.x = pack_h2(v.x, v.y);
    o.y = pack_h2(v.z, v.w);
    dst[i] = o;
}

// ---------------------------------------------------------------------------
// Fused QKV GEMM + RoPE epilogue.
// C[4096, 6144] = x[4096,4096] * Wf[6144,4096]^T ; cols 0..4095 -> q (rope),
// 4096..5119 -> k (rope), 5120..6143 -> v. 128x128 tile, BK=32, 2-stage.
// ---------------------------------------------------------------------------
#define GW 20   // 32-bit words per smem row (32 data halfs + 8 pad)

__global__ __launch_bounds__(256) void gemm_qkv(
    const __half* __restrict__ A, const __half* __restrict__ Bm,
    __half* __restrict__ Qo, __half* __restrict__ Ko, __half* __restrict__ Vo,
    const float* __restrict__ fc, const float* __restrict__ fs)
{
    __shared__ alignas(16) uint32_t As[2][128 * GW];
    __shared__ alignas(16) uint32_t Bs[2][128 * GW];

    const int K = D_;
    const int tid = threadIdx.x;
    const int lane = tid & 31;
    const int wid = tid >> 5;
    const int g = lane >> 2;
    const int t = lane & 3;
    const int tile = lane >> 3;
    const int trow = lane & 7;
    const int wm = (wid >> 1) * 32;
    const int wn = (wid & 1) * 64;
    const int m0 = blockIdx.y * 128;
    const int n0 = blockIdx.x * 128;

    const __half* Ap = A + (size_t)m0 * K;
    const __half* Bp = Bm + (size_t)n0 * K;

    float acc[2][8][4];
#pragma unroll
    for (int mi = 0; mi < 2; mi++)
#pragma unroll
        for (int ni = 0; ni < 8; ni++)
#pragma unroll
            for (int j = 0; j < 4; j++) acc[mi][ni][j] = 0.f;

    const int NT = K / 32;

    auto load_stage = [&](int s, int kt) {
        uint32_t ab = smem_u32(&As[s][0]);
        uint32_t bb = smem_u32(&Bs[s][0]);
#pragma unroll
        for (int i = 0; i < 2; i++) {
            int idx = tid + i * 256;
            int row = idx >> 2;
            int ch = idx & 3;
            cp16s(ab + row * (GW * 4) + ch * 16, Ap + (size_t)row * K + kt * 32 + ch * 8);
            cp16s(bb + row * (GW * 4) + ch * 16, Bp + (size_t)row * K + kt * 32 + ch * 8);
        }
    };

    load_stage(0, 0);
    CP_COMMIT();

    for (int kt = 0; kt < NT; kt++) {
        if (kt + 1 < NT) {
            load_stage((kt + 1) & 1, kt + 1);
            CP_COMMIT();
            cp_wait<1>();
        } else {
            cp_wait<0>();
        }
        __syncthreads();

        const int s = kt & 1;
#pragma unroll
        for (int ks = 0; ks < 2; ks++) {
            uint32_t af[2][4];
#pragma unroll
            for (int mi = 0; mi < 2; mi++) {
                uint32_t addr = smem_u32(&As[s][
                    (wm + mi * 16 + trow + ((tile & 1) << 3)) * GW
                    + ks * 8 + ((tile >> 1) << 2)]);
                ldsm_x4(af[mi][0], af[mi][1], af[mi][2], af[mi][3], addr);
            }
#pragma unroll
            for (int nip = 0; nip < 4; nip++) {
                uint32_t b0, b1, b2, b3;
                uint32_t addr = smem_u32(&Bs[s][
                    (wn + nip * 16 + trow + ((tile >> 1) << 3)) * GW
                    + ks * 8 + ((tile & 1) << 2)]);
                ldsm_x4(b0, b1, b2, b3, addr);
                uint32_t bfa[2] = {b0, b1};
                uint32_t bfb[2] = {b2, b3};
                mma_f16(acc[0][2 * nip], af[0], bfa, acc[0][2 * nip]);
                mma_f16(acc[1][2 * nip], af[1], bfa, acc[1][2 * nip]);
                mma_f16(acc[0][2 * nip + 1], af[0], bfb, acc[0][2 * nip + 1]);
                mma_f16(acc[1][2 * nip + 1], af[1], bfb, acc[1][2 * nip + 1]);
            }
        }
        __syncthreads();
    }

    // epilogue: rope (q,k) + split write
#pragma unroll
    for (int mi = 0; mi < 2; mi++)
#pragma unroll
        for (int ni = 0; ni < 8; ni++)
#pragma unroll
            for (int half_ = 0; half_ < 2; half_++) {
                int row = m0 + wm + mi * 16 + g + half_ * 8;
                int col = n0 + wn + ni * 8 + 2 * t;
                float e = acc[mi][ni][half_ * 2 + 0];
                float o = acc[mi][ni][half_ * 2 + 1];
                if (col < 5120) {   // rope for q and k
                    int tpos = row & (T_ - 1);
                    int p = (col & 127) >> 1;
                    float c = fc[tpos * 64 + p];
                    float sn = fs[tpos * 64 + p];
                    float e2 = e * c - o * sn;
                    o = e * sn + o * c;
                    e = e2;
                }
                uint32_t pk = pack_h2(e, o);
                if (col < 4096)
                    *(uint32_t*)&Qo[(size_t)row * D_ + col] = pk;
                else if (col < 5120)
                    *(uint32_t*)&Ko[(size_t)row * 1024 + (col - 4096)] = pk;
                else
                    *(uint32_t*)&Vo[(size_t)row * 1024 + (col - 5120)] = pk;
            }
}

// ---------------------------------------------------------------------------
// fp16 GEMM NT (O-projection): C[M,N] = A[M,K] * B[N,K]^T, fp32 out.
// ---------------------------------------------------------------------------
__global__ __launch_bounds__(256) void gemm_h(
    const __half* __restrict__ A, const __half* __restrict__ Bm,
    float* __restrict__ Cf, int M, int N, int K)
{
    __shared__ alignas(16) uint32_t As[2][128 * GW];
    __shared__ alignas(16) uint32_t Bs[2][128 * GW];

    const int tid = threadIdx.x;
    const int lane = tid & 31;
    const int wid = tid >> 5;
    const int g = lane >> 2;
    const int t = lane & 3;
    const int tile = lane >> 3;
    const int trow = lane & 7;
    const int wm = (wid >> 1) * 32;
    const int wn = (wid & 1) * 64;
    const int m0 = blockIdx.y * 128;
    const int n0 = blockIdx.x * 128;

    const __half* Ap = A + (size_t)m0 * K;
    const __half* Bp = Bm + (size_t)n0 * K;

    float acc[2][8][4];
#pragma unroll
    for (int mi = 0; mi < 2; mi++)
#pragma unroll
        for (int ni = 0; ni < 8; ni++)
#pragma unroll
            for (int j = 0; j < 4; j++) acc[mi][ni][j] = 0.f;

    const int NT = K / 32;

    auto load_stage = [&](int s, int kt) {
        uint32_t ab = smem_u32(&As[s][0]);
        uint32_t bb = smem_u32(&Bs[s][0]);
#pragma unroll
        for (int i = 0; i < 2; i++) {
            int idx = tid + i * 256;
            int row = idx >> 2;
            int ch = idx & 3;
            cp16s(ab + row * (GW * 4) + ch * 16, Ap + (size_t)row * K + kt * 32 + ch * 8);
            cp16s(bb + row * (GW * 4) + ch * 16, Bp + (size_t)row * K + kt * 32 + ch * 8);
        }
    };

    load_stage(0, 0);
    CP_COMMIT();

    for (int kt = 0; kt < NT; kt++) {
        if (kt + 1 < NT) {
            load_stage((kt + 1) & 1, kt + 1);
            CP_COMMIT();
            cp_wait<1>();
        } else {
            cp_wait<0>();
        }
        __syncthreads();

        const int s = kt & 1;
#pragma unroll
        for (int ks = 0; ks < 2; ks++) {
            uint32_t af[2][4];
#pragma unroll
            for (int mi = 0; mi < 2; mi++) {
                uint32_t addr = smem_u32(&As[s][
                    (wm + mi * 16 + trow + ((tile & 1) << 3)) * GW
                    + ks * 8 + ((tile >> 1) << 2)]);
                ldsm_x4(af[mi][0], af[mi][1], af[mi][2], af[mi][3], addr);
            }
#pragma unroll
            for (int nip = 0; nip < 4; nip++) {
                uint32_t b0, b1, b2, b3;
                uint32_t addr = smem_u32(&Bs[s][
                    (wn + nip * 16 + trow + ((tile >> 1) << 3)) * GW
                    + ks * 8 + ((tile & 1) << 2)]);
                ldsm_x4(b0, b1, b2, b3, addr);
                uint32_t bfa[2] = {b0, b1};
                uint32_t bfb[2] = {b2, b3};
                mma_f16(acc[0][2 * nip], af[0], bfa, acc[0][2 * nip]);
                mma_f16(acc[1][2 * nip], af[1], bfa, acc[1][2 * nip]);
                mma_f16(acc[0][2 * nip + 1], af[0], bfb, acc[0][2 * nip + 1]);
                mma_f16(acc[1][2 * nip + 1], af[1], bfb, acc[1][2 * nip + 1]);
            }
        }
        __syncthreads();
    }

#pragma unroll
    for (int mi = 0; mi < 2; mi++)
#pragma unroll
        for (int ni = 0; ni < 8; ni++) {
            int row = m0 + wm + mi * 16 + g;
            int col = n0 + wn + ni * 8 + 2 * t;
            *(float2*)&Cf[(size_t)row * N + col] = make_float2(acc[mi][ni][0], acc[mi][ni][1]);
            *(float2*)&Cf[(size_t)(row + 8) * N + col] = make_float2(acc[mi][ni][2], acc[mi][ni][3]);
        }
}

// ---------------------------------------------------------------------------
// Flash attention, fp16 mma.m16n8k16 + ldmatrix.
// Block: 128 q-rows, 8 warps. KV tile 64 keys. K double-buffered, V single.
// ---------------------------------------------------------------------------
#define QW 68    // words per Q/K/V smem row (64 halfs x2 data + 8 pad words)
#define PW 36    // words per P row (64 halfs data + 8 pad)
#define FL_WORDS (128 * QW + 2 * 64 * QW + 64 * QW + 128 * PW)
#define FL_BYTES (FL_WORDS * 4)

__global__ __launch_bounds__(256, 1) void flash_h(
    const __half* __restrict__ Q, const __half* __restrict__ Kg,
    const __half* __restrict__ Vg, __half* __restrict__ Og)
{
    extern __shared__ uint32_t sm[];
    uint32_t* Qs = sm;                          // 128 x QW
    uint32_t* Ks = sm + 128 * QW;               // 2 x 64 x QW
    uint32_t* Vs = Ks + 2 * 64 * QW;            // 64 x QW
    uint32_t* Ps = Vs + 64 * QW;                // 128 x PW

    const int tid = threadIdx.x;
    const int lane = tid & 31;
    const int wid = tid >> 5;
    const int g = lane >> 2;
    const int t = lane & 3;
    const int tile = lane >> 3;
    const int trow = lane & 7;
    const int wq = wid * 16;

    const int q0 = blockIdx.x * 128;
    const int bh = blockIdx.y;
    const int b = bh >> 5;
    const int h = bh & 31;
    const int kvh = h >> 2;

    const float qs = 0.08838834764831845f * 1.4426950408889634f;  // scale*log2e

    const __half* Qb = Q + (((size_t)(b * T_ + q0)) * H_ + h) * HD_;
    const __half* Kb = Kg + (((size_t)b * T_) * KVH_ + kvh) * HD_;
    const __half* Vb = Vg + (((size_t)b * T_) * KVH_ + kvh) * HD_;

    const uint32_t qsb = smem_u32(Qs);
    const uint32_t ksb = smem_u32(Ks);
    const uint32_t vsb = smem_u32(Vs);

    // prologue: Q, K0, V0
    {
#pragma unroll
        for (int i = 0; i < 8; i++) {
            int idx = tid + i * 256;
            int r = idx >> 4;
            int ch = idx & 15;
            cp16s(qsb + r * (QW * 4) + ch * 16, Qb + (size_t)r * (H_ * HD_) + ch * 8);
        }
        CP_COMMIT();
#pragma unroll
        for (int i = 0; i < 4; i++) {
            int idx = tid + i * 256;
            int r = idx >> 4;
            int ch = idx & 15;
            cp16s(ksb + r * (QW * 4) + ch * 16, Kb + (size_t)r * (KVH_ * HD_) + ch * 8);
        }
        CP_COMMIT();
#pragma unroll
        for (int i = 0; i < 4; i++) {
            int idx = tid + i * 256;
            int r = idx >> 4;
            int ch = idx & 15;
            cp16s(vsb + r * (QW * 4) + ch * 16, Vb + (size_t)r * (KVH_ * HD_) + ch * 8);
        }
        CP_COMMIT();
    }

    float o[16][4];
#pragma unroll
    for (int nt = 0; nt < 16; nt++)
#pragma unroll
        for (int j = 0; j < 4; j++) o[nt][j] = 0.f;

    float m0s = -1e30f, m1s = -1e30f;
    float l0s = 0.f, l1s = 0.f;

    const int NKT = T_ / 64;
    for (int kt = 0; kt < NKT; kt++) {
        const int s = kt & 1;
        const uint32_t* Kcur = Ks + s * 64 * QW;
        cp_wait<1>();
        __syncthreads();

        // S = Q K^T : per warp m16 x n64, k=128
        float sv[8][4];
#pragma unroll
        for (int ni = 0; ni < 8; ni++)
#pragma unroll
            for (int j = 0; j < 4; j++) sv[ni][j] = 0.f;

#pragma unroll
        for (int ks = 0; ks < 8; ks++) {
            uint32_t af[4];
            {
                uint32_t addr = qsb +
                    ((wq + trow + ((tile & 1) << 3)) * QW
                     + ks * 8 + ((tile >> 1) << 2)) * 4;
                ldsm_x4(af[0], af[1], af[2], af[3], addr);
            }
#pragma unroll
            for (int nip = 0; nip < 4; nip++) {
                uint32_t b0, b1, b2, b3;
                uint32_t addr = smem_u32(&Kcur[
                    (nip * 16 + trow + ((tile >> 1) << 3)) * QW
                    + ks * 8 + ((tile & 1) << 2)]);
                ldsm_x4(b0, b1, b2, b3, addr);
                uint32_t bfa[2] = {b0, b1};
                uint32_t bfb[2] = {b2, b3};
                mma_f16(sv[2 * nip], af, bfa, sv[2 * nip]);
                mma_f16(sv[2 * nip + 1], af, bfb, sv[2 * nip + 1]);
            }
        }

        // scale + online softmax (base-2)
        float mx0 = -1e30f, mx1 = -1e30f;
#pragma unroll
        for (int ni = 0; ni < 8; ni++) {
            sv[ni][0] *= qs; sv[ni][1] *= qs; sv[ni][2] *= qs; sv[ni][3] *= qs;
            mx0 = fmaxf(mx0, fmaxf(sv[ni][0], sv[ni][1]));
            mx1 = fmaxf(mx1, fmaxf(sv[ni][2], sv[ni][3]));
        }
        mx0 = fmaxf(mx0, __shfl_xor_sync(0xffffffffu, mx0, 1));
        mx0 = fmaxf(mx0, __shfl_xor_sync(0xffffffffu, mx0, 2));
        mx1 = fmaxf(mx1, __shfl_xor_sync(0xffffffffu, mx1, 1));
        mx1 = fmaxf(mx1, __shfl_xor_sync(0xffffffffu, mx1, 2));

        float mn0 = fmaxf(m0s, mx0);
        float mn1 = fmaxf(m1s, mx1);
        float alpha0 = ex2f(m0s - mn0);
        float alpha1 = ex2f(m1s - mn1);
        m0s = mn0; m1s = mn1;

        float ls0 = 0.f, ls1 = 0.f;
#pragma unroll
        for (int ni = 0; ni < 8; ni++) {
            float p0 = ex2f(sv[ni][0] - mn0);
            float p1 = ex2f(sv[ni][1] - mn0);
            float p2 = ex2f(sv[ni][2] - mn1);
            float p3 = ex2f(sv[ni][3] - mn1);
            ls0 += p0 + p1;
            ls1 += p2 + p3;
            Ps[(wq + g) * PW + ni * 4 + t] = pack_h2(p0, p1);
            Ps[(wq + g + 8) * PW + ni * 4 + t] = pack_h2(p2, p3);
        }
        ls0 += __shfl_xor_sync(0xffffffffu, ls0, 1);
        ls0 += __shfl_xor_sync(0xffffffffu, ls0, 2);
        ls1 += __shfl_xor_sync(0xffffffffu, ls1, 1);
        ls1 += __shfl_xor_sync(0xffffffffu, ls1, 2);
        l0s = l0s * alpha0 + ls0;
        l1s = l1s * alpha1 + ls1;

#pragma unroll
        for (int nt = 0; nt < 16; nt++) {
            o[nt][0] *= alpha0; o[nt][1] *= alpha0;
            o[nt][2] *= alpha1; o[nt][3] *= alpha1;
        }

        cp_wait<0>();
        __syncthreads();

        // launch K(kt+1) while PV runs
        if (kt + 1 < NKT) {
            const __half* kp = Kb + (size_t)(kt + 1) * 64 * (KVH_ * HD_);
            uint32_t kdst = ksb + (s ^ 1) * 64 * QW * 4;
#pragma unroll
            for (int i = 0; i < 4; i++) {
                int idx = tid + i * 256;
                int r = idx >> 4;
                int ch = idx & 15;
                cp16s(kdst + r * (QW * 4) + ch * 16, kp + (size_t)r * (KVH_ * HD_) + ch * 8);
            }
            CP_COMMIT();
        }

        // O += P * V : per warp m16 x n128, k=64
        {
            const int sub = lane >> 3;
            const int rr = lane & 7;
#pragma unroll
            for (int ks = 0; ks < 4; ks++) {
                uint32_t af[4];
                af[0] = Ps[(wq + g) * PW + ks * 8 + t];
                af[1] = Ps[(wq + g + 8) * PW + ks * 8 + t];
                af[2] = Ps[(wq + g) * PW + ks * 8 + t + 4];
                af[3] = Ps[(wq + g + 8) * PW + ks * 8 + t + 4];
#pragma unroll
                for (int ntp = 0; ntp < 8; ntp++) {
                    int rowa = ks * 16 + rr + (sub & 1) * 8;
                    int cola = ntp * 16 + (sub >> 1) * 8;
                    uint32_t addr = vsb + rowa * (QW * 4) + cola * 2;
                    uint32_t b0, b1, b2, b3;
                    ldsm_x4_t(b0, b1, b2, b3, addr);
                    uint32_t be[2] = {b0, b1};
                    uint32_t bo[2] = {b2, b3};
                    mma_f16(o[2 * ntp], af, be, o[2 * ntp]);
                    mma_f16(o[2 * ntp + 1], af, bo, o[2 * ntp + 1]);
                }
            }
        }
        __syncthreads();

        // launch V(kt+1)
        if (kt + 1 < NKT) {
            const __half* vp = Vb + (size_t)(kt + 1) * 64 * (KVH_ * HD_);
#pragma unroll
            for (int i = 0; i < 4; i++) {
                int idx = tid + i * 256;
                int r = idx >> 4;
                int ch = idx & 15;
                cp16s(vsb + r * (QW * 4) + ch * 16, vp + (size_t)r * (KVH_ * HD_) + ch * 8);
            }
            CP_COMMIT();
        }
    }

    // normalize + write ctx (half) [B,T,H*HD]
    float inv0 = 1.0f / l0s;
    float inv1 = 1.0f / l1s;
#pragma unroll
    for (int nt = 0; nt < 16; nt++) {
        size_t row0 = (size_t)(b * T_ + q0 + wq + g);
        size_t row1 = row0 + 8;
        int col = h * HD_ + nt * 8 + 2 * t;
        *(uint32_t*)&Og[row0 * D_ + col] = pack_h2(o[nt][0] * inv0, o[nt][1] * inv0);
        *(uint32_t*)&Og[row1 * D_ + col] = pack_h2(o[nt][2] * inv1, o[nt][3] * inv1);
    }
}

// ---------------------------------------------------------------------------
// kernel_launch
// Inputs: 0:x 1:wq 2:wk 3:wv 4:wo 5:freqs_cos 6:freqs_sin 7:start_pos
// ---------------------------------------------------------------------------
extern "C" void kernel_launch(void* const* d_in, const int* in_sizes, int n_in,
                              void* d_out, int out_size)
{
    const float* x  = (const float*)d_in[0];
    const float* wq = (const float*)d_in[1];
    const float* wk = (const float*)d_in[2];
    const float* wv = (const float*)d_in[3];
    const float* wo = (const float*)d_in[4];
    const float* fc = (const float*)d_in[5];
    const float* fs = (const float*)d_in[6];
    float* out = (float*)d_out;

    __half *qh, *kh, *vh, *ctxh, *xh, *wf, *woh;
    cudaGetSymbolAddress((void**)&qh,   g_qh);
    cudaGetSymbolAddress((void**)&kh,   g_kh);
    cudaGetSymbolAddress((void**)&vh,   g_vh);
    cudaGetSymbolAddress((void**)&ctxh, g_ctxh);
    cudaGetSymbolAddress((void**)&xh,   g_xh);
    cudaGetSymbolAddress((void**)&wf,   g_wf);
    cudaGetSymbolAddress((void**)&woh,  g_woh);

    cudaFuncSetAttribute(flash_h,
                         cudaFuncAttributeMaxDynamicSharedMemorySize, FL_BYTES);

    // convert inputs to fp16; wq/wk/wv concatenated into g_wf
    {
        int n4x = BT_ * D_ / 4;
        f2h_kernel<<<(n4x + 255) / 256, 256>>>((const float4*)x,  (uint2*)xh,  n4x);
        int n4q = D_ * D_ / 4;
        f2h_kernel<<<(n4q + 255) / 256, 256>>>((const float4*)wq, (uint2*)wf, n4q);
        int n4k = (KVH_ * HD_) * D_ / 4;
        f2h_kernel<<<(n4k + 255) / 256, 256>>>((const float4*)wk,
            (uint2*)(wf + (size_t)D_ * D_), n4k);
        f2h_kernel<<<(n4k + 255) / 256, 256>>>((const float4*)wv,
            (uint2*)(wf + (size_t)(D_ + KVH_ * HD_) * D_), n4k);
        f2h_kernel<<<(n4q + 255) / 256, 256>>>((const float4*)wo, (uint2*)woh, n4q);
    }

    // fused QKV projection + RoPE epilogue
    {
        dim3 g(NQKV / 128, BT_ / 128);
        gemm_qkv<<<g, 256>>>(xh, wf, qh, kh, vh, fc, fs);
    }

    // Flash attention (fp16 mma + ldmatrix)
    {
        dim3 g(T_ / 128, B_ * H_);
        flash_h<<<g, 256, FL_BYTES>>>(qh, kh, vh, ctxh);
    }

    // Output projection (fp16 in, fp32 out)
    {
        dim3 go(D_ / 128, BT_ / 128);
        gemm_h<<<go, 256>>>(ctxh, woh, out, BT_, D_, D_);
    }
}

// round 16
// speedup vs baseline: 1.3777x; 1.3777x over previous
#include <cuda_runtime.h>
#include <cuda_fp16.h>
#include <cstdint>
#include <math.h>

// Problem constants
#define B_  2
#define T_  2048
#define D_  4096
#define H_  32
#define KVH_ 8
#define HD_ 128
#define BT_ (B_ * T_)            // 4096

// Scratch (allocation-free: __device__ globals) — fp16 pipeline
__device__ __half g_qh[(size_t)BT_ * H_ * HD_];     // [B,T,H,HD]
__device__ __half g_kvh[(size_t)BT_ * 2 * KVH_ * HD_]; // [BT, 2048]: k|v fused cols
__device__ __half g_ctxh[(size_t)BT_ * H_ * HD_];   // [B,T,H*HD]
__device__ __half g_xh[(size_t)BT_ * D_];
__device__ __half g_wqh[(size_t)D_ * D_];
__device__ __half g_wkvh[(size_t)(2 * KVH_ * HD_) * D_];  // [wk;wv]
__device__ __half g_woh[(size_t)D_ * D_];

// ---------------------------------------------------------------------------
// helpers
// ---------------------------------------------------------------------------
__device__ __forceinline__ float ex2f(float x) {
    float y;
    asm("ex2.approx.ftz.f32 %0, %1;" : "=f"(y) : "f"(x));
    return y;
}
// D(16x8,f32) = A(16x16,f16) * B(16x8,f16,col) + C
__device__ __forceinline__ void mma_f16(float* d, const uint32_t* a,
                                        const uint32_t* b, const float* c) {
    asm volatile(
        "mma.sync.aligned.m16n8k16.row.col.f32.f16.f16.f32 "
        "{%0,%1,%2,%3}, {%4,%5,%6,%7}, {%8,%9}, {%10,%11,%12,%13};"
        : "=f"(d[0]), "=f"(d[1]), "=f"(d[2]), "=f"(d[3])
        : "r"(a[0]), "r"(a[1]), "r"(a[2]), "r"(a[3]),
          "r"(b[0]), "r"(b[1]),
          "f"(c[0]), "f"(c[1]), "f"(c[2]), "f"(c[3]));
}
__device__ __forceinline__ void ldsm_x4_t(uint32_t& r0, uint32_t& r1,
                                          uint32_t& r2, uint32_t& r3, uint32_t addr) {
    asm volatile("ldmatrix.sync.aligned.m8n8.x4.trans.shared.b16 {%0,%1,%2,%3}, [%4];"
                 : "=r"(r0), "=r"(r1), "=r"(r2), "=r"(r3) : "r"(addr));
}
__device__ __forceinline__ void cp16s(uint32_t saddr, const void* gmem_src) {
    asm volatile("cp.async.cg.shared.global [%0], [%1], 16;" :: "r"(saddr), "l"(gmem_src));
}
#define CP_COMMIT() asm volatile("cp.async.commit_group;" ::: "memory")
template <int N>
__device__ __forceinline__ void cp_wait() {
    asm volatile("cp.async.wait_group %0;" :: "n"(N) : "memory");
}
__device__ __forceinline__ uint32_t smem_u32(const void* p) {
    return (uint32_t)__cvta_generic_to_shared(p);
}
__device__ __forceinline__ uint32_t pack_h2(float a, float b) {
    __half2 h = __floats2half2_rn(a, b);
    return *(uint32_t*)&h;
}

// ---------------------------------------------------------------------------
// fp32 -> fp16 conversion pass
// ---------------------------------------------------------------------------
__global__ void f2h_kernel(const float4* __restrict__ src,
                           uint2* __restrict__ dst, int n4)
{
    int i = blockIdx.x * blockDim.x + threadIdx.x;
    if (i >= n4) return;
    float4 v = src[i];
    uint2 o;
    o.x = pack_h2(v.x, v.y);
    o.y = pack_h2(v.z, v.w);
    dst[i] = o;
}

// ---------------------------------------------------------------------------
// fp16 GEMM NT: C[M,N] = A[M,K] * B[N,K]^T (half in, fp32 accum).
// 128x128 tile, BK=32, 2-stage cp.async, SINGLE barrier per K-slice.
// 256 threads (8 warps, 4m x 2n), warp tile 32x64 via m16n8k16.
// out_half: write half, else fp32.
// ---------------------------------------------------------------------------
#define GW 20   // 32-bit words per smem row (32 data halfs + 8 pad)

__global__ __launch_bounds__(256) void gemm_h(
    const __half* __restrict__ A, const __half* __restrict__ Bm,
    void* __restrict__ Cout, int M, int N, int K, int out_half)
{
    __shared__ alignas(16) uint32_t As[2][128 * GW];
    __shared__ alignas(16) uint32_t Bs[2][128 * GW];

    const int tid = threadIdx.x;
    const int lane = tid & 31;
    const int wid = tid >> 5;
    const int g = lane >> 2;
    const int t = lane & 3;
    const int wm = (wid >> 1) * 32;
    const int wn = (wid & 1) * 64;
    const int m0 = blockIdx.y * 128;
    const int n0 = blockIdx.x * 128;

    const __half* Ap = A + (size_t)m0 * K;
    const __half* Bp = Bm + (size_t)n0 * K;

    float acc[2][8][4];
#pragma unroll
    for (int mi = 0; mi < 2; mi++)
#pragma unroll
        for (int ni = 0; ni < 8; ni++)
#pragma unroll
            for (int j = 0; j < 4; j++) acc[mi][ni][j] = 0.f;

    const int NT = K / 32;

    // stage loader: A,B 128 rows x 32 halfs (4 x 16B chunks per row)
    auto load_stage = [&](int s, int kt) {
        uint32_t ab = smem_u32(&As[s][0]);
        uint32_t bb = smem_u32(&Bs[s][0]);
#pragma unroll
        for (int i = 0; i < 2; i++) {
            int idx = tid + i * 256;
            int row = idx >> 2;
            int ch = idx & 3;
            cp16s(ab + row * (GW * 4) + ch * 16, Ap + (size_t)row * K + kt * 32 + ch * 8);
            cp16s(bb + row * (GW * 4) + ch * 16, Bp + (size_t)row * K + kt * 32 + ch * 8);
        }
    };

    load_stage(0, 0);
    CP_COMMIT();

    for (int kt = 0; kt < NT; kt++) {
        const int s = kt & 1;
        cp_wait<0>();        // stage kt resident (only group outstanding)
        __syncthreads();     // all warps finished iter kt-1 (buffer s^1 free)

        if (kt + 1 < NT) {   // prefetch into s^1 overlaps compute below
            load_stage(s ^ 1, kt + 1);
            CP_COMMIT();
        }

#pragma unroll
        for (int ks = 0; ks < 2; ks++) {
            uint32_t af[2][4];
#pragma unroll
            for (int mi = 0; mi < 2; mi++) {
                int mr = wm + mi * 16;
                af[mi][0] = As[s][(mr + g) * GW + ks * 8 + t];
                af[mi][1] = As[s][(mr + g + 8) * GW + ks * 8 + t];
                af[mi][2] = As[s][(mr + g) * GW + ks * 8 + t + 4];
                af[mi][3] = As[s][(mr + g + 8) * GW + ks * 8 + t + 4];
            }
#pragma unroll
            for (int ni = 0; ni < 8; ni++) {
                uint32_t bf[2];
                bf[0] = Bs[s][(wn + ni * 8 + g) * GW + ks * 8 + t];
                bf[1] = Bs[s][(wn + ni * 8 + g) * GW + ks * 8 + t + 4];
                mma_f16(acc[0][ni], af[0], bf, acc[0][ni]);
                mma_f16(acc[1][ni], af[1], bf, acc[1][ni]);
            }
        }
    }

    if (out_half) {
        __half* Ch = (__half*)Cout;
#pragma unroll
        for (int mi = 0; mi < 2; mi++)
#pragma unroll
            for (int ni = 0; ni < 8; ni++) {
                int row = m0 + wm + mi * 16 + g;
                int col = n0 + wn + ni * 8 + 2 * t;
                *(uint32_t*)&Ch[(size_t)row * N + col] = pack_h2(acc[mi][ni][0], acc[mi][ni][1]);
                *(uint32_t*)&Ch[(size_t)(row + 8) * N + col] = pack_h2(acc[mi][ni][2], acc[mi][ni][3]);
            }
    } else {
        float* Cf = (float*)Cout;
#pragma unroll
        for (int mi = 0; mi < 2; mi++)
#pragma unroll
            for (int ni = 0; ni < 8; ni++) {
                int row = m0 + wm + mi * 16 + g;
                int col = n0 + wn + ni * 8 + 2 * t;
                *(float2*)&Cf[(size_t)row * N + col] = make_float2(acc[mi][ni][0], acc[mi][ni][1]);
                *(float2*)&Cf[(size_t)(row + 8) * N + col] = make_float2(acc[mi][ni][2], acc[mi][ni][3]);
            }
    }
}

// ---------------------------------------------------------------------------
// RoPE on half data: one thread per (b,t,h,pair).
// rowstride_h2: row stride of the tensor in half2 units.
// ---------------------------------------------------------------------------
__global__ void rope_h_kernel(__half2* __restrict__ tns,
                              const float* __restrict__ fcos,
                              const float* __restrict__ fsin,
                              int NH, int rowstride_h2, int total)
{
    int i = blockIdx.x * blockDim.x + threadIdx.x;
    if (i >= total) return;
    int p = i & 63;                     // pair within head
    int rem = i >> 6;                   // b*T*NH + t*NH + h
    int bt = rem / NH;
    int hh = rem - bt * NH;
    int t = bt & (T_ - 1);
    float c = fcos[t * 64 + p];
    float s = fsin[t * 64 + p];
    size_t off = (size_t)bt * rowstride_h2 + hh * 64 + p;
    float2 v = __half22float2(tns[off]);
    tns[off] = __floats2half2_rn(v.x * c - v.y * s, v.x * s + v.y * c);
}

// ---------------------------------------------------------------------------
// Flash attention, fp16 mma.m16n8k16 (R12-proven structure).
// Block: 128 q-rows, 8 warps. KV tile 64 keys. K double-buffered, V single.
// KV rows at stride 2048 halfs (fused buffer: k = cols 0..1023, v = 1024..2047).
// ---------------------------------------------------------------------------
#define QW 68    // words per Q/K/V smem row (128 halfs data + 8 pad)
#define PW 36    // words per P row (64 halfs data + 8 pad)
#define FL_WORDS (128 * QW + 2 * 64 * QW + 64 * QW + 128 * PW)
#define FL_BYTES (FL_WORDS * 4)
#define KVSTRIDE (2 * KVH_ * HD_)   // 2048 halfs per token row

__global__ __launch_bounds__(256, 1) void flash_h(
    const __half* __restrict__ Q, const __half* __restrict__ KVg,
    __half* __restrict__ Og)
{
    extern __shared__ uint32_t sm[];
    uint32_t* Qs = sm;                          // 128 x QW
    uint32_t* Ks = sm + 128 * QW;               // 2 x 64 x QW
    uint32_t* Vs = Ks + 2 * 64 * QW;            // 64 x QW
    uint32_t* Ps = Vs + 64 * QW;                // 128 x PW

    const int tid = threadIdx.x;
    const int lane = tid & 31;
    const int wid = tid >> 5;
    const int g = lane >> 2;
    const int t = lane & 3;
    const int wq = wid * 16;

    const int q0 = blockIdx.x * 128;
    const int bh = blockIdx.y;
    const int b = bh >> 5;
    const int h = bh & 31;
    const int kvh = h >> 2;

    const float qs = 0.08838834764831845f * 1.4426950408889634f;  // scale*log2e

    const __half* Qb = Q + (((size_t)(b * T_ + q0)) * H_ + h) * HD_;
    const __half* Kb = KVg + ((size_t)b * T_) * KVSTRIDE + kvh * HD_;
    const __half* Vb = Kb + KVH_ * HD_;   // v part: +1024 cols

    const uint32_t qsb = smem_u32(Qs);
    const uint32_t ksb = smem_u32(Ks);
    const uint32_t vsb = smem_u32(Vs);

    // prologue: Q, K0, V0
    {
#pragma unroll
        for (int i = 0; i < 8; i++) {     // 128 rows x 16 chunks
            int idx = tid + i * 256;
            int r = idx >> 4;
            int ch = idx & 15;
            cp16s(qsb + r * (QW * 4) + ch * 16, Qb + (size_t)r * (H_ * HD_) + ch * 8);
        }
        CP_COMMIT();
#pragma unroll
        for (int i = 0; i < 4; i++) {     // 64 rows x 16 chunks
            int idx = tid + i * 256;
            int r = idx >> 4;
            int ch = idx & 15;
            cp16s(ksb + r * (QW * 4) + ch * 16, Kb + (size_t)r * KVSTRIDE + ch * 8);
        }
        CP_COMMIT();
#pragma unroll
        for (int i = 0; i < 4; i++) {
            int idx = tid + i * 256;
            int r = idx >> 4;
            int ch = idx & 15;
            cp16s(vsb + r * (QW * 4) + ch * 16, Vb + (size_t)r * KVSTRIDE + ch * 8);
        }
        CP_COMMIT();
    }

    float o[16][4];
#pragma unroll
    for (int nt = 0; nt < 16; nt++)
#pragma unroll
        for (int j = 0; j < 4; j++) o[nt][j] = 0.f;

    float m0s = -1e30f, m1s = -1e30f;
    float l0s = 0.f, l1s = 0.f;

    const int NKT = T_ / 64;
    for (int kt = 0; kt < NKT; kt++) {
        const int s = kt & 1;
        const uint32_t* Kcur = Ks + s * 64 * QW;
        cp_wait<1>();      // Q + K(kt) resident (V(kt) may be in flight)
        __syncthreads();

        // S = Q K^T : per warp m16 x n64, k=128 (8 k16 steps)
        float sv[8][4];
#pragma unroll
        for (int ni = 0; ni < 8; ni++)
#pragma unroll
            for (int j = 0; j < 4; j++) sv[ni][j] = 0.f;

#pragma unroll
        for (int ks = 0; ks < 8; ks++) {
            uint32_t af[4];
            af[0] = Qs[(wq + g) * QW + ks * 8 + t];
            af[1] = Qs[(wq + g + 8) * QW + ks * 8 + t];
            af[2] = Qs[(wq + g) * QW + ks * 8 + t + 4];
            af[3] = Qs[(wq + g + 8) * QW + ks * 8 + t + 4];
#pragma unroll
            for (int ni = 0; ni < 8; ni++) {
                uint32_t bf[2];
                bf[0] = Kcur[(ni * 8 + g) * QW + ks * 8 + t];
                bf[1] = Kcur[(ni * 8 + g) * QW + ks * 8 + t + 4];
                mma_f16(sv[ni], af, bf, sv[ni]);
            }
        }

        // scale + online softmax (base-2)
        float mx0 = -1e30f, mx1 = -1e30f;
#pragma unroll
        for (int ni = 0; ni < 8; ni++) {
            sv[ni][0] *= qs; sv[ni][1] *= qs; sv[ni][2] *= qs; sv[ni][3] *= qs;
            mx0 = fmaxf(mx0, fmaxf(sv[ni][0], sv[ni][1]));
            mx1 = fmaxf(mx1, fmaxf(sv[ni][2], sv[ni][3]));
        }
        mx0 = fmaxf(mx0, __shfl_xor_sync(0xffffffffu, mx0, 1));
        mx0 = fmaxf(mx0, __shfl_xor_sync(0xffffffffu, mx0, 2));
        mx1 = fmaxf(mx1, __shfl_xor_sync(0xffffffffu, mx1, 1));
        mx1 = fmaxf(mx1, __shfl_xor_sync(0xffffffffu, mx1, 2));

        float mn0 = fmaxf(m0s, mx0);
        float mn1 = fmaxf(m1s, mx1);
        float alpha0 = ex2f(m0s - mn0);
        float alpha1 = ex2f(m1s - mn1);
        m0s = mn0; m1s = mn1;

        float ls0 = 0.f, ls1 = 0.f;
#pragma unroll
        for (int ni = 0; ni < 8; ni++) {
            float p0 = ex2f(sv[ni][0] - mn0);
            float p1 = ex2f(sv[ni][1] - mn0);
            float p2 = ex2f(sv[ni][2] - mn1);
            float p3 = ex2f(sv[ni][3] - mn1);
            ls0 += p0 + p1;
            ls1 += p2 + p3;
            Ps[(wq + g) * PW + ni * 4 + t] = pack_h2(p0, p1);
            Ps[(wq + g + 8) * PW + ni * 4 + t] = pack_h2(p2, p3);
        }
        ls0 += __shfl_xor_sync(0xffffffffu, ls0, 1);
        ls0 += __shfl_xor_sync(0xffffffffu, ls0, 2);
        ls1 += __shfl_xor_sync(0xffffffffu, ls1, 1);
        ls1 += __shfl_xor_sync(0xffffffffu, ls1, 2);
        l0s = l0s * alpha0 + ls0;
        l1s = l1s * alpha1 + ls1;

#pragma unroll
        for (int nt = 0; nt < 16; nt++) {
            o[nt][0] *= alpha0; o[nt][1] *= alpha0;
            o[nt][2] *= alpha1; o[nt][3] *= alpha1;
        }

        cp_wait<0>();      // V(kt) resident
        __syncthreads();

        // launch K(kt+1) while PV runs
        if (kt + 1 < NKT) {
            const __half* kp = Kb + (size_t)(kt + 1) * 64 * KVSTRIDE;
            uint32_t kdst = ksb + (s ^ 1) * 64 * QW * 4;
#pragma unroll
            for (int i = 0; i < 4; i++) {
                int idx = tid + i * 256;
                int r = idx >> 4;
                int ch = idx & 15;
                cp16s(kdst + r * (QW * 4) + ch * 16, kp + (size_t)r * KVSTRIDE + ch * 8);
            }
            CP_COMMIT();
        }

        // O += P * V : per warp m16 x n128, k=64 (4 k16 steps)
        {
            const int sub = lane >> 3;
            const int rr = lane & 7;
#pragma unroll
            for (int ks = 0; ks < 4; ks++) {
                uint32_t af[4];
                af[0] = Ps[(wq + g) * PW + ks * 8 + t];
                af[1] = Ps[(wq + g + 8) * PW + ks * 8 + t];
                af[2] = Ps[(wq + g) * PW + ks * 8 + t + 4];
                af[3] = Ps[(wq + g + 8) * PW + ks * 8 + t + 4];
#pragma unroll
                for (int ntp = 0; ntp < 8; ntp++) {
                    int rowa = ks * 16 + rr + (sub & 1) * 8;
                    int cola = ntp * 16 + (sub >> 1) * 8;
                    uint32_t addr = vsb + rowa * (QW * 4) + cola * 2;
                    uint32_t b0, b1, b2, b3;
                    ldsm_x4_t(b0, b1, b2, b3, addr);
                    uint32_t be[2] = {b0, b1};
                    uint32_t bo[2] = {b2, b3};
                    mma_f16(o[2 * ntp], af, be, o[2 * ntp]);
                    mma_f16(o[2 * ntp + 1], af, bo, o[2 * ntp + 1]);
                }
            }
        }
        __syncthreads();

        // launch V(kt+1)
        if (kt + 1 < NKT) {
            const __half* vp = Vb + (size_t)(kt + 1) * 64 * KVSTRIDE;
#pragma unroll
            for (int i = 0; i < 4; i++) {
                int idx = tid + i * 256;
                int r = idx >> 4;
                int ch = idx & 15;
                cp16s(vsb + r * (QW * 4) + ch * 16, vp + (size_t)r * KVSTRIDE + ch * 8);
            }
            CP_COMMIT();
        }
    }

    // normalize + write ctx (half) [B,T,H*HD]
    float inv0 = 1.0f / l0s;
    float inv1 = 1.0f / l1s;
#pragma unroll
    for (int nt = 0; nt < 16; nt++) {
        size_t row0 = (size_t)(b * T_ + q0 + wq + g);
        size_t row1 = row0 + 8;
        int col = h * HD_ + nt * 8 + 2 * t;
        *(uint32_t*)&Og[row0 * D_ + col] = pack_h2(o[nt][0] * inv0, o[nt][1] * inv0);
        *(uint32_t*)&Og[row1 * D_ + col] = pack_h2(o[nt][2] * inv1, o[nt][3] * inv1);
    }
}

// ---------------------------------------------------------------------------
// kernel_launch
// Inputs: 0:x 1:wq 2:wk 3:wv 4:wo 5:freqs_cos 6:freqs_sin 7:start_pos
// ---------------------------------------------------------------------------
extern "C" void kernel_launch(void* const* d_in, const int* in_sizes, int n_in,
                              void* d_out, int out_size)
{
    const float* x  = (const float*)d_in[0];
    const float* wq = (const float*)d_in[1];
    const float* wk = (const float*)d_in[2];
    const float* wv = (const float*)d_in[3];
    const float* wo = (const float*)d_in[4];
    const float* fc = (const float*)d_in[5];
    const float* fs = (const float*)d_in[6];
    float* out = (float*)d_out;

    __half *qh, *kvh, *ctxh, *xh, *wqh, *wkvh, *woh;
    cudaGetSymbolAddress((void**)&qh,   g_qh);
    cudaGetSymbolAddress((void**)&kvh,  g_kvh);
    cudaGetSymbolAddress((void**)&ctxh, g_ctxh);
    cudaGetSymbolAddress((void**)&xh,   g_xh);
    cudaGetSymbolAddress((void**)&wqh,  g_wqh);
    cudaGetSymbolAddress((void**)&wkvh, g_wkvh);
    cudaGetSymbolAddress((void**)&woh,  g_woh);

    cudaFuncSetAttribute(flash_h,
                         cudaFuncAttributeMaxDynamicSharedMemorySize, FL_BYTES);

    // convert inputs to fp16 (wk, wv concatenated)
    {
        int n4x = BT_ * D_ / 4;
        f2h_kernel<<<(n4x + 255) / 256, 256>>>((const float4*)x,  (uint2*)xh,  n4x);
        int n4q = D_ * D_ / 4;
        f2h_kernel<<<(n4q + 255) / 256, 256>>>((const float4*)wq, (uint2*)wqh, n4q);
        int n4k = (KVH_ * HD_) * D_ / 4;
        f2h_kernel<<<(n4k + 255) / 256, 256>>>((const float4*)wk, (uint2*)wkvh, n4k);
        f2h_kernel<<<(n4k + 255) / 256, 256>>>((const float4*)wv,
            (uint2*)(wkvh + (size_t)(KVH_ * HD_) * D_), n4k);
        f2h_kernel<<<(n4q + 255) / 256, 256>>>((const float4*)wo, (uint2*)woh, n4q);
    }

    // Q projection + fused KV projection
    {
        dim3 gq(D_ / 128, BT_ / 128);
        gemm_h<<<gq, 256>>>(xh, wqh, qh, BT_, D_, D_, 1);
        dim3 gkv((2 * KVH_ * HD_) / 128, BT_ / 128);
        gemm_h<<<gkv, 256>>>(xh, wkvh, kvh, BT_, 2 * KVH_ * HD_, D_, 1);
    }

    // RoPE on q and on the k-part of the fused kv buffer
    {
        int totq = BT_ * H_ * (HD_ / 2);
        rope_h_kernel<<<(totq + 255) / 256, 256>>>((__half2*)qh, fc, fs, H_, H_ * 64, totq);
        int totk = BT_ * KVH_ * (HD_ / 2);
        rope_h_kernel<<<(totk + 255) / 256, 256>>>((__half2*)kvh, fc, fs, KVH_,
                                                   KVSTRIDE / 2, totk);
    }

    // Flash attention
    {
        dim3 g(T_ / 128, B_ * H_);
        flash_h<<<g, 256, FL_BYTES>>>(qh, kvh, ctxh);
    }

    // Output projection (fp16 in, fp32 out)
    {
        dim3 go(D_ / 128, BT_ / 128);
        gemm_h<<<go, 256>>>(ctxh, woh, out, BT_, D_, D_, 0);
    }
}